// round 15
// baseline (speedup 1.0000x reference)
#include <cuda_runtime.h>
#include <cuda_fp16.h>
#include <cstdint>

#define NBLK 64
#define NTHR 256
#define HDIM 512
#define BDIM 128
#define TIN  512
#define TOT  544
#define BH   (BDIM*HDIM)

// SMEM byte offsets
#define SA    0           // A tile: 128 rows x 1024B fp16, swizzled (gate staging aliases it)
#define SW1   131072      // 3 weight tiles: 32 rows x 1024B fp16 = 32KB each
#define SW2I  163840
#define SW2H  196608
#define SMISC 229376
#define SXS   (SMISC)         // 128 f32
#define SRED  (SMISC+512)     // 256 f32
#define SB1   (SMISC+1536)    // 32 f32
#define SWIH  (SMISC+1664)    // 32 f32
#define SB2   (SMISC+1792)    // 32 f32
#define SBOUT (SMISC+1920)    // 1 f32
#define SMEM_BYTES (SMISC+2048)   // 231424

__device__ __half  g_h1f[2][BH];   // [buf][b][k] fp16
__device__ __half  g_h2f[2][BH];
__device__ float   g_h2n[2][BH];   // [buf][b][k] fp32 (output dots)
__device__ float   g_h2t[2][BH];   // [buf][k][b] fp32 (future-phase dot)
__device__ unsigned g_flags[NBLK];

static __device__ __forceinline__ uint32_t smem_u32(const void* p){
    uint32_t a;
    asm("{ .reg .u64 t; cvta.to.shared.u64 t, %1; cvt.u32.u64 %0, t; }" : "=r"(a) : "l"(p));
    return a;
}
static __device__ __forceinline__ float sigf(float x){ return 1.0f/(1.0f+__expf(-x)); }
static __device__ __forceinline__ float tfast(float x){ return 2.0f*sigf(2.0f*x) - 1.0f; }

// Flag-array grid barrier: no contended atomics. release-store own flag,
// thread i (<NBLK) acquire-polls flag[i]; __syncthreads broadcasts.
static __device__ __forceinline__ void grid_barrier(unsigned& gen){
    const unsigned tgt = gen + 1;
    __syncthreads();
    if (threadIdx.x == 0)
        asm volatile("st.release.gpu.u32 [%0], %1;" :: "l"(&g_flags[blockIdx.x]), "r"(tgt) : "memory");
    if (threadIdx.x < NBLK){
        unsigned v;
        do { asm volatile("ld.acquire.gpu.u32 %0, [%1];" : "=r"(v) : "l"(&g_flags[threadIdx.x])); }
        while (v < tgt);
    }
    gen = tgt;
    __syncthreads();
}

#define TEAM_BAR(team) asm volatile("bar.sync %0, 128;" :: "r"(1+(team)) : "memory")

// load 64 batch rows (team half) of h [.][512] fp16 into SMEM A tile, L2-only.
static __device__ __forceinline__ void load_half(uint32_t saAddr,
                                                 const __half* __restrict__ src,
                                                 int team, int tt){
    #pragma unroll
    for (int j = 0; j < 32; ++j){
        int i  = tt + j*128;
        int m  = team*64 + (i >> 6);
        int u8 = i & 63;
        uint32_t dst = (saAddr + (uint32_t)(m*1024 + u8*16)) ^ (uint32_t)((m & 7) << 4);
        const __half* s = src + (size_t)m*HDIM + u8*8;
        asm volatile("cp.async.cg.shared.global [%0], [%1], 16;"
                     :: "r"(dst), "l"(s) : "memory");
    }
    asm volatile("cp.async.commit_group;" ::: "memory");
    asm volatile("cp.async.wait_group 0;" ::: "memory");
}

// warp GEMM: acc[4][4] += A(16 rows x 512) * B(32 x 512)^T  (N=32, k-tiles of 16)
static __device__ __forceinline__ void warp_gemm(float (&acc)[4][4],
                                                 uint32_t aBase, uint32_t aswz,
                                                 uint32_t bBase, uint32_t bswz){
    #pragma unroll 4
    for (int kt = 0; kt < 32; ++kt){
        uint32_t aa  = (aBase + (uint32_t)(kt*32)) ^ aswz;
        uint32_t ba0 = (bBase + (uint32_t)(kt*32)) ^ bswz;
        uint32_t ba1 = (bBase + 16384u + (uint32_t)(kt*32)) ^ bswz;
        uint32_t a0,a1,a2,a3, b0,b1,b2,b3, b4,b5,b6,b7;
        asm volatile("ldmatrix.sync.aligned.m8n8.x4.shared.b16 {%0,%1,%2,%3}, [%4];"
            : "=r"(a0),"=r"(a1),"=r"(a2),"=r"(a3) : "r"(aa));
        asm volatile("ldmatrix.sync.aligned.m8n8.x4.shared.b16 {%0,%1,%2,%3}, [%4];"
            : "=r"(b0),"=r"(b1),"=r"(b2),"=r"(b3) : "r"(ba0));
        asm volatile("ldmatrix.sync.aligned.m8n8.x4.shared.b16 {%0,%1,%2,%3}, [%4];"
            : "=r"(b4),"=r"(b5),"=r"(b6),"=r"(b7) : "r"(ba1));
        asm volatile("mma.sync.aligned.m16n8k16.row.col.f32.f16.f16.f32 "
            "{%0,%1,%2,%3}, {%4,%5,%6,%7}, {%8,%9}, {%0,%1,%2,%3};"
            : "+f"(acc[0][0]),"+f"(acc[0][1]),"+f"(acc[0][2]),"+f"(acc[0][3])
            : "r"(a0),"r"(a1),"r"(a2),"r"(a3), "r"(b0),"r"(b1));
        asm volatile("mma.sync.aligned.m16n8k16.row.col.f32.f16.f16.f32 "
            "{%0,%1,%2,%3}, {%4,%5,%6,%7}, {%8,%9}, {%0,%1,%2,%3};"
            : "+f"(acc[1][0]),"+f"(acc[1][1]),"+f"(acc[1][2]),"+f"(acc[1][3])
            : "r"(a0),"r"(a1),"r"(a2),"r"(a3), "r"(b2),"r"(b3));
        asm volatile("mma.sync.aligned.m16n8k16.row.col.f32.f16.f16.f32 "
            "{%0,%1,%2,%3}, {%4,%5,%6,%7}, {%8,%9}, {%0,%1,%2,%3};"
            : "+f"(acc[2][0]),"+f"(acc[2][1]),"+f"(acc[2][2]),"+f"(acc[2][3])
            : "r"(a0),"r"(a1),"r"(a2),"r"(a3), "r"(b4),"r"(b5));
        asm volatile("mma.sync.aligned.m16n8k16.row.col.f32.f16.f16.f32 "
            "{%0,%1,%2,%3}, {%4,%5,%6,%7}, {%8,%9}, {%0,%1,%2,%3};"
            : "+f"(acc[3][0]),"+f"(acc[3][1]),"+f"(acc[3][2]),"+f"(acc[3][3])
            : "r"(a0),"r"(a1),"r"(a2),"r"(a3), "r"(b6),"r"(b7));
    }
}

// stage 16x32 gates (warp) into st, aliased over this warp's A rows
static __device__ __forceinline__ void stage_gates(float* st, float (&acc)[4][4],
                                                   int eg, int etq){
    #pragma unroll
    for (int ni = 0; ni < 4; ++ni){
        *reinterpret_cast<float2*>(&st[eg*32     + ni*8 + 2*etq]) = make_float2(acc[ni][0], acc[ni][1]);
        *reinterpret_cast<float2*>(&st[(eg+8)*32 + ni*8 + 2*etq]) = make_float2(acc[ni][2], acc[ni][3]);
    }
}

// out[b] = dot(h2n[b,:], Wout) + bias; one warp, lane passed explicitly
static __device__ __forceinline__ void out_one(
    const float* __restrict__ h2n, const float* __restrict__ Wout,
    float bout, int b, int lane, float* dst)
{
    const float4* hp = reinterpret_cast<const float4*>(h2n) + (size_t)b*(HDIM/4);
    const float4* wp = reinterpret_cast<const float4*>(Wout);
    float s = 0.f;
    #pragma unroll
    for (int q = lane; q < HDIM/4; q += 32){
        float4 hv = __ldcg(hp + q); float4 w = __ldg(wp + q);
        s += hv.x*w.x + hv.y*w.y + hv.z*w.z + hv.w*w.w;
    }
    #pragma unroll
    for (int o = 16; o; o >>= 1) s += __shfl_xor_sync(0xffffffffu, s, o);
    if (lane == 0) *dst = s + bout;
}

__global__ void lstm_reset(){ if (threadIdx.x < NBLK) g_flags[threadIdx.x] = 0u; }

__global__ void __launch_bounds__(NTHR, 1) lstm_persist(
    const float* __restrict__ xg,
    const float* __restrict__ Wih1, const float* __restrict__ Whh1,
    const float* __restrict__ bih1, const float* __restrict__ bhh1,
    const float* __restrict__ Wih2, const float* __restrict__ Whh2,
    const float* __restrict__ bih2, const float* __restrict__ bhh2,
    const float* __restrict__ Wout, const float* __restrict__ boutp,
    float* __restrict__ outg)
{
    extern __shared__ __align__(128) char sm[];
    const uint32_t sb = smem_u32(sm);
    float* s_xs  = reinterpret_cast<float*>(sm + SXS);
    float* s_red = reinterpret_cast<float*>(sm + SRED);
    float* s_b1  = reinterpret_cast<float*>(sm + SB1);
    float* s_wih = reinterpret_cast<float*>(sm + SWIH);
    float* s_b2  = reinterpret_cast<float*>(sm + SB2);
    float* s_bo  = reinterpret_cast<float*>(sm + SBOUT);

    const int tid  = threadIdx.x;
    const int blk  = blockIdx.x;
    const int U0   = blk * 8;            // this CTA owns 8 hidden units
    const int wid  = tid >> 5;
    const int lane = tid & 31;
    const int team = tid >> 7;
    const int tt   = tid & 127;

    // ldmatrix lane addressing
    const int grp = lane >> 3, l7 = lane & 7;
    const int am  = (wid << 4) + l7 + ((grp & 1) << 3);
    const uint32_t aBase = sb + SA + (uint32_t)(am*1024 + ((grp >> 1) << 4));
    const uint32_t aswz  = (uint32_t)((am & 7) << 4);
    const int bn  = l7 + ((grp >> 1) << 3);
    const uint32_t bOff  = (uint32_t)(bn*1024 + ((grp & 1) << 4));
    const uint32_t bswz  = (uint32_t)((bn & 7) << 4);
    const uint32_t bB1   = sb + SW1  + bOff;
    const uint32_t bB2i  = sb + SW2I + bOff;
    const uint32_t bB2h  = sb + SW2H + bOff;

    // ---- one-time staging: 32 gate rows x 512 K fp16, swizzled ----
    for (int idx = tid; idx < 32*HDIM; idx += NTHR){
        int n = idx >> 9, k = idx & 511;
        int uu = n >> 2, gg = n & 3;
        size_t j = (size_t)(gg*HDIM + U0 + uu) * HDIM + k;
        uint32_t rel = (uint32_t)(n*1024 + 2*k);
        uint32_t sw  = (uint32_t)((n & 7) << 4);
        unsigned short v1 = __half_as_ushort(__float2half(Whh1[j]));
        unsigned short v2 = __half_as_ushort(__float2half(Wih2[j]));
        unsigned short v3 = __half_as_ushort(__float2half(Whh2[j]));
        asm volatile("st.shared.u16 [%0], %1;" :: "r"((sb + SW1  + rel) ^ sw), "h"(v1));
        asm volatile("st.shared.u16 [%0], %1;" :: "r"((sb + SW2I + rel) ^ sw), "h"(v2));
        asm volatile("st.shared.u16 [%0], %1;" :: "r"((sb + SW2H + rel) ^ sw), "h"(v3));
    }
    if (tid < 32){
        int uu = tid >> 2, gg = tid & 3;
        int j = gg*HDIM + U0 + uu;
        s_b1[tid]  = bih1[j] + bhh1[j];
        s_b2[tid]  = bih2[j] + bhh2[j];
        s_wih[tid] = Wih1[j];
    }
    if (tid == 0) s_bo[0] = boutp[0];
    for (int i = tid; i < 8*BDIM; i += NTHR){
        int kk = U0 + (i >> 7), bb = i & 127;
        size_t on = (size_t)bb*HDIM + kk;
        size_t ot = (size_t)kk*BDIM + bb;
        g_h1f[0][on] = __float2half(0.f); g_h1f[1][on] = __float2half(0.f);
        g_h2f[0][on] = __float2half(0.f); g_h2f[1][on] = __float2half(0.f);
        g_h2n[0][on] = 0.f; g_h2n[1][on] = 0.f;
        g_h2t[0][ot] = 0.f; g_h2t[1][ot] = 0.f;
    }
    unsigned gen = 0;
    grid_barrier(gen);

    // epilogue indices
    const int eg = lane >> 2, etq = lane & 3;          // staging write coords
    const int bl = lane >> 1, uh = (lane & 1);         // read: row bl, units uh*4..+3
    const int bglob = (wid << 4) + bl;
    float* st = reinterpret_cast<float*>(sm + SA + wid*16384);  // aliases this warp's A rows
    float c1[4] = {0.f,0.f,0.f,0.f}, c2[4] = {0.f,0.f,0.f,0.f};

    for (int t = 0; t < TOT; ++t){
        const int cur = t & 1, prv = cur ^ 1;

        // ---- Phase X ----
        if (t < TIN){
            if (tid < BDIM) s_xs[tid] = xg[(size_t)tid*TIN + t];
            if (t > 0 && wid < 2)
                out_one(g_h2n[prv], Wout, s_bo[0], 2*blk + wid, lane,
                        outg + (size_t)(2*blk + wid)*TOT + (t-1));
        } else {
            int b = tid & 127, half = tid >> 7;
            const float* hp = g_h2t[prv] + (size_t)half*(HDIM/2)*BDIM + b;
            const float* wp = Wout + half*(HDIM/2);
            float s = 0.f;
            #pragma unroll 8
            for (int q = 0; q < HDIM/2; ++q)
                s += __ldcg(hp + (size_t)q*BDIM) * __ldg(wp + q);
            s_red[tid] = s;
            __syncthreads();
            if (tid < BDIM) s_xs[tid] = s_red[tid] + s_red[tid+128] + s_bo[0];
        }
        __syncthreads();
        if (t >= TIN && tid == 0){
            outg[(size_t)(2*blk  )*TOT + (t-1)] = s_xs[2*blk];
            outg[(size_t)(2*blk+1)*TOT + (t-1)] = s_xs[2*blk+1];
        }

        // ---- P1: gates1 = h1_prev @ W_hh1^T ----
        {
            load_half(sb + SA, g_h1f[prv], team, tt);
            TEAM_BAR(team);
            float acc[4][4] = {};
            warp_gemm(acc, aBase, aswz, bB1, bswz);
            stage_gates(st, acc, eg, etq);
            __syncwarp();
            const float xv = s_xs[bglob];
            float hh[4];
            #pragma unroll
            for (int un = 0; un < 4; ++un){
                float4 g  = *reinterpret_cast<float4*>(&st[bl*32 + uh*16 + un*4]);
                float4 bb = *reinterpret_cast<float4*>(&s_b1[uh*16 + un*4]);
                float4 ww = *reinterpret_cast<float4*>(&s_wih[uh*16 + un*4]);
                float vi = g.x + bb.x + xv*ww.x;
                float vf = g.y + bb.y + xv*ww.y;
                float vg = g.z + bb.z + xv*ww.z;
                float vo = g.w + bb.w + xv*ww.w;
                c1[un] = sigf(vf)*c1[un] + sigf(vi)*tfast(vg);
                hh[un] = sigf(vo)*tfast(c1[un]);
            }
            size_t base = (size_t)bglob*HDIM + U0 + uh*4;
            *reinterpret_cast<__half2*>(&g_h1f[cur][base  ]) = __floats2half2_rn(hh[0], hh[1]);
            *reinterpret_cast<__half2*>(&g_h1f[cur][base+2]) = __floats2half2_rn(hh[2], hh[3]);
        }
        grid_barrier(gen);

        // ---- P2: gates2 = h1_new @ W_ih2^T + h2_prev @ W_hh2^T ----
        {
            float acc[4][4] = {};
            load_half(sb + SA, g_h1f[cur], team, tt);
            TEAM_BAR(team);
            warp_gemm(acc, aBase, aswz, bB2i, bswz);
            TEAM_BAR(team);
            load_half(sb + SA, g_h2f[prv], team, tt);
            TEAM_BAR(team);
            warp_gemm(acc, aBase, aswz, bB2h, bswz);
            stage_gates(st, acc, eg, etq);
            __syncwarp();
            float hh[4];
            #pragma unroll
            for (int un = 0; un < 4; ++un){
                float4 g  = *reinterpret_cast<float4*>(&st[bl*32 + uh*16 + un*4]);
                float4 bb = *reinterpret_cast<float4*>(&s_b2[uh*16 + un*4]);
                float vi = g.x + bb.x, vf = g.y + bb.y;
                float vg = g.z + bb.z, vo = g.w + bb.w;
                c2[un] = sigf(vf)*c2[un] + sigf(vi)*tfast(vg);
                hh[un] = sigf(vo)*tfast(c2[un]);
            }
            size_t base = (size_t)bglob*HDIM + U0 + uh*4;
            *reinterpret_cast<__half2*>(&g_h2f[cur][base  ]) = __floats2half2_rn(hh[0], hh[1]);
            *reinterpret_cast<__half2*>(&g_h2f[cur][base+2]) = __floats2half2_rn(hh[2], hh[3]);
            *reinterpret_cast<float4*>(&g_h2n[cur][base]) = make_float4(hh[0], hh[1], hh[2], hh[3]);
            #pragma unroll
            for (int un = 0; un < 4; ++un)
                g_h2t[cur][(size_t)(U0 + uh*4 + un)*BDIM + bglob] = hh[un];
        }
        grid_barrier(gen);
    }

    if (wid < 2)
        out_one(g_h2n[(TOT-1)&1], Wout, s_bo[0], 2*blk + wid, lane,
                outg + (size_t)(2*blk + wid)*TOT + (TOT-1));
}

extern "C" void kernel_launch(void* const* d_in, const int* in_sizes, int n_in,
                              void* d_out, int out_size){
    (void)in_sizes; (void)n_in; (void)out_size;
    cudaFuncSetAttribute(lstm_persist,
                         cudaFuncAttributeMaxDynamicSharedMemorySize, SMEM_BYTES);
    const float* x    = (const float*)d_in[0];
    const float* Wih1 = (const float*)d_in[1];
    const float* Whh1 = (const float*)d_in[2];
    const float* bih1 = (const float*)d_in[3];
    const float* bhh1 = (const float*)d_in[4];
    const float* Wih2 = (const float*)d_in[5];
    const float* Whh2 = (const float*)d_in[6];
    const float* bih2 = (const float*)d_in[7];
    const float* bhh2 = (const float*)d_in[8];
    const float* Wout = (const float*)d_in[9];
    const float* bout = (const float*)d_in[10];
    float* out = (float*)d_out;

    lstm_reset<<<1, NBLK>>>();
    lstm_persist<<<NBLK, NTHR, SMEM_BYTES>>>(
        x, Wih1, Whh1, bih1, bhh1, Wih2, Whh2, bih2, bhh2, Wout, bout, out);
}

// round 16
// speedup vs baseline: 1.0700x; 1.0700x over previous
#include <cuda_runtime.h>
#include <cuda_fp16.h>
#include <cstdint>

#define NBLK 128
#define NTHR 256
#define HDIM 512
#define BDIM 128
#define TIN  512
#define TOT  544
#define BH   (BDIM*HDIM)

// SMEM byte offsets (all 1KB-aligned)
#define SA    0           // A tile: 128 rows x 1024B fp16, swizzled
#define SW1   131072      // 3 weight tiles: 16 rows x 1024B fp16 each
#define SW2I  147456
#define SW2H  163840
#define SGATE 180224      // 8 warps x 16x16 f32 = 8192
#define SMISC 188416
#define SXS   (SMISC)         // 128 f32
#define SRED  (SMISC+512)     // 256 f32
#define SB1   (SMISC+1536)    // 16 f32
#define SWIH  (SMISC+1600)    // 16 f32
#define SB2   (SMISC+1664)    // 16 f32
#define SBOUT (SMISC+1728)    // 1 f32
#define SMEM_BYTES (SMISC+2048)

__device__ __half  g_h1f[2][BH];   // [buf][b][k] fp16
__device__ __half  g_h2f[2][BH];
__device__ float   g_h2n[2][BH];   // [buf][b][k] fp32 (output dots)
__device__ float   g_h2t[2][BH];   // [buf][k][b] fp32 (future-phase dot)
__device__ unsigned g_flags[NBLK];

static __device__ __forceinline__ uint32_t smem_u32(const void* p){
    uint32_t a;
    asm("{ .reg .u64 t; cvta.to.shared.u64 t, %1; cvt.u32.u64 %0, t; }" : "=r"(a) : "l"(p));
    return a;
}
static __device__ __forceinline__ float sigf(float x){ return 1.0f/(1.0f+__expf(-x)); }
static __device__ __forceinline__ float tfast(float x){ return 2.0f*sigf(2.0f*x) - 1.0f; }

// Flag-array grid barrier: no contended atomics.
static __device__ __forceinline__ void grid_barrier(unsigned& gen){
    const unsigned tgt = gen + 1;
    __syncthreads();
    if (threadIdx.x == 0)
        asm volatile("st.release.gpu.u32 [%0], %1;"
                     :: "l"(&g_flags[blockIdx.x]), "r"(tgt) : "memory");
    if (threadIdx.x < NBLK){
        unsigned v;
        do { asm volatile("ld.acquire.gpu.u32 %0, [%1];"
                          : "=r"(v) : "l"(&g_flags[threadIdx.x])); }
        while (v < tgt);
    }
    gen = tgt;
    __syncthreads();
}

#define TEAM_BAR(team) asm volatile("bar.sync %0, 128;" :: "r"(1+(team)) : "memory")

// issue cp.async for 64 batch rows (team half) of h [.][512] fp16 -> SMEM A, L2-only.
static __device__ __forceinline__ void load_issue(uint32_t saAddr,
                                                  const __half* __restrict__ src,
                                                  int team, int tt){
    #pragma unroll
    for (int j = 0; j < 32; ++j){
        int i  = tt + j*128;
        int m  = team*64 + (i >> 6);
        int u8 = i & 63;
        uint32_t dst = (saAddr + (uint32_t)(m*1024 + u8*16)) ^ (uint32_t)((m & 7) << 4);
        const __half* s = src + (size_t)m*HDIM + u8*8;
        asm volatile("cp.async.cg.shared.global [%0], [%1], 16;"
                     :: "r"(dst), "l"(s) : "memory");
    }
    asm volatile("cp.async.commit_group;" ::: "memory");
}
static __device__ __forceinline__ void load_wait(){
    asm volatile("cp.async.wait_group 0;" ::: "memory");
}

// warp GEMM: acc[2][4] += A(16 rows x 512) * B(16 x 512)^T, k-tiles of 16
static __device__ __forceinline__ void warp_gemm(float (&acc)[2][4],
                                                 uint32_t aBase, uint32_t aswz,
                                                 uint32_t bBase, uint32_t bswz){
    #pragma unroll 8
    for (int kt = 0; kt < 32; ++kt){
        uint32_t aa = (aBase + (uint32_t)(kt*32)) ^ aswz;
        uint32_t ba = (bBase + (uint32_t)(kt*32)) ^ bswz;
        uint32_t a0,a1,a2,a3, b0,b1,b2,b3;
        asm volatile("ldmatrix.sync.aligned.m8n8.x4.shared.b16 {%0,%1,%2,%3}, [%4];"
            : "=r"(a0),"=r"(a1),"=r"(a2),"=r"(a3) : "r"(aa));
        asm volatile("ldmatrix.sync.aligned.m8n8.x4.shared.b16 {%0,%1,%2,%3}, [%4];"
            : "=r"(b0),"=r"(b1),"=r"(b2),"=r"(b3) : "r"(ba));
        asm volatile("mma.sync.aligned.m16n8k16.row.col.f32.f16.f16.f32 "
            "{%0,%1,%2,%3}, {%4,%5,%6,%7}, {%8,%9}, {%0,%1,%2,%3};"
            : "+f"(acc[0][0]),"+f"(acc[0][1]),"+f"(acc[0][2]),"+f"(acc[0][3])
            : "r"(a0),"r"(a1),"r"(a2),"r"(a3), "r"(b0),"r"(b1));
        asm volatile("mma.sync.aligned.m16n8k16.row.col.f32.f16.f16.f32 "
            "{%0,%1,%2,%3}, {%4,%5,%6,%7}, {%8,%9}, {%0,%1,%2,%3};"
            : "+f"(acc[1][0]),"+f"(acc[1][1]),"+f"(acc[1][2]),"+f"(acc[1][3])
            : "r"(a0),"r"(a1),"r"(a2),"r"(a3), "r"(b2),"r"(b3));
    }
}

// out[b] = dot(h2n[b,:], Wout) + bias; warp 0 (tid<32)
static __device__ __forceinline__ void out_one(
    const float* __restrict__ h2n, const float* __restrict__ Wout,
    float bout, int b, float* dst)
{
    const int lane = threadIdx.x;
    const float4* hp = reinterpret_cast<const float4*>(h2n) + (size_t)b*(HDIM/4);
    const float4* wp = reinterpret_cast<const float4*>(Wout);
    float s = 0.f;
    #pragma unroll
    for (int q = lane; q < HDIM/4; q += 32){
        float4 hv = __ldcg(hp + q); float4 w = __ldg(wp + q);
        s += hv.x*w.x + hv.y*w.y + hv.z*w.z + hv.w*w.w;
    }
    #pragma unroll
    for (int o = 16; o; o >>= 1) s += __shfl_xor_sync(0xffffffffu, s, o);
    if (lane == 0) *dst = s + bout;
}

__global__ void lstm_reset(){ if (threadIdx.x < NBLK) g_flags[threadIdx.x] = 0u; }

__global__ void __launch_bounds__(NTHR, 1) lstm_persist(
    const float* __restrict__ xg,
    const float* __restrict__ Wih1, const float* __restrict__ Whh1,
    const float* __restrict__ bih1, const float* __restrict__ bhh1,
    const float* __restrict__ Wih2, const float* __restrict__ Whh2,
    const float* __restrict__ bih2, const float* __restrict__ bhh2,
    const float* __restrict__ Wout, const float* __restrict__ boutp,
    float* __restrict__ outg)
{
    extern __shared__ __align__(128) char sm[];
    const uint32_t sb = smem_u32(sm);
    float* s_gate = reinterpret_cast<float*>(sm + SGATE);
    float* s_xs   = reinterpret_cast<float*>(sm + SXS);
    float* s_red  = reinterpret_cast<float*>(sm + SRED);
    float* s_b1   = reinterpret_cast<float*>(sm + SB1);
    float* s_wih  = reinterpret_cast<float*>(sm + SWIH);
    float* s_b2   = reinterpret_cast<float*>(sm + SB2);
    float* s_bo   = reinterpret_cast<float*>(sm + SBOUT);

    const int tid  = threadIdx.x;
    const int blk  = blockIdx.x;
    const int U0   = blk * 4;
    const int wid  = tid >> 5;
    const int lane = tid & 31;
    const int team = tid >> 7;
    const int tt   = tid & 127;

    // ldmatrix lane addressing
    const int grp = lane >> 3, l7 = lane & 7;
    const int am  = (wid << 4) + l7 + ((grp & 1) << 3);
    const uint32_t aBase = sb + SA + (uint32_t)(am*1024 + ((grp >> 1) << 4));
    const uint32_t aswz  = (uint32_t)((am & 7) << 4);
    const int bn  = l7 + ((grp >> 1) << 3);
    const uint32_t bOff  = (uint32_t)(bn*1024 + ((grp & 1) << 4));
    const uint32_t bswz  = (uint32_t)((bn & 7) << 4);
    const uint32_t bB1   = sb + SW1  + bOff;
    const uint32_t bB2i  = sb + SW2I + bOff;
    const uint32_t bB2h  = sb + SW2H + bOff;

    // ---- one-time staging ----
    for (int idx = tid; idx < 16*HDIM; idx += NTHR){
        int n = idx >> 9, k = idx & 511;
        int uu = n >> 2, gg = n & 3;
        size_t j = (size_t)(gg*HDIM + U0 + uu) * HDIM + k;
        uint32_t rel = (uint32_t)(n*1024 + 2*k);
        uint32_t sw  = (uint32_t)((n & 7) << 4);
        unsigned short v1 = __half_as_ushort(__float2half(Whh1[j]));
        unsigned short v2 = __half_as_ushort(__float2half(Wih2[j]));
        unsigned short v3 = __half_as_ushort(__float2half(Whh2[j]));
        asm volatile("st.shared.u16 [%0], %1;" :: "r"((sb + SW1  + rel) ^ sw), "h"(v1));
        asm volatile("st.shared.u16 [%0], %1;" :: "r"((sb + SW2I + rel) ^ sw), "h"(v2));
        asm volatile("st.shared.u16 [%0], %1;" :: "r"((sb + SW2H + rel) ^ sw), "h"(v3));
    }
    if (tid < 16){
        int uu = tid >> 2, gg = tid & 3;
        int j = gg*HDIM + U0 + uu;
        s_b1[tid]  = bih1[j] + bhh1[j];
        s_b2[tid]  = bih2[j] + bhh2[j];
        s_wih[tid] = Wih1[j];
    }
    if (tid == 0) s_bo[0] = boutp[0];
    for (int i = tid; i < 4*BDIM; i += NTHR){
        int kk = U0 + (i >> 7), bb = i & 127;
        size_t on = (size_t)bb*HDIM + kk;
        size_t ot = (size_t)kk*BDIM + bb;
        g_h1f[0][on] = __float2half(0.f); g_h1f[1][on] = __float2half(0.f);
        g_h2f[0][on] = __float2half(0.f); g_h2f[1][on] = __float2half(0.f);
        g_h2n[0][on] = 0.f; g_h2n[1][on] = 0.f;
        g_h2t[0][ot] = 0.f; g_h2t[1][ot] = 0.f;
    }
    unsigned gen = 0;
    grid_barrier(gen);               // gmem zeros visible chip-wide

    // preload A with h1f[1] (= prv for t=0)
    load_issue(sb + SA, g_h1f[1], team, tt);
    load_wait();
    __syncthreads();

    // epilogue indices
    const int eg = lane >> 2, etq = lane & 3;
    const int bl = lane >> 1, u0 = (lane & 1) * 2;
    const int bglob = (wid << 4) + bl;
    float* st = s_gate + wid*256;
    float c1a = 0.f, c1b = 0.f, c2a = 0.f, c2b = 0.f;

    for (int t = 0; t < TOT; ++t){
        const int cur = t & 1, prv = cur ^ 1;

        // ---- Phase X ----
        if (t < TIN){
            if (tid < BDIM) s_xs[tid] = xg[(size_t)tid*TIN + t];
            if (t > 0 && tid < 32)
                out_one(g_h2n[prv], Wout, s_bo[0], blk, outg + (size_t)blk*TOT + (t-1));
        } else {
            int b = tid & 127, half = tid >> 7;
            const float* hp = g_h2t[prv] + (size_t)half*(HDIM/2)*BDIM + b;
            const float* wp = Wout + half*(HDIM/2);
            float s = 0.f;
            #pragma unroll 8
            for (int q = 0; q < HDIM/2; ++q)
                s += __ldcg(hp + (size_t)q*BDIM) * __ldg(wp + q);
            s_red[tid] = s;
            __syncthreads();
            if (tid < BDIM) s_xs[tid] = s_red[tid] + s_red[tid+128] + s_bo[0];
        }
        __syncthreads();
        if (t >= TIN && tid == 0) outg[(size_t)blk*TOT + (t-1)] = s_xs[blk];

        // ---- P1: gates1 = h1_prv @ W_hh1^T   (A already holds h1_prv) ----
        {
            float acc[2][4] = {};
            warp_gemm(acc, aBase, aswz, bB1, bswz);
            TEAM_BAR(team);                       // team A-reads done
            load_issue(sb + SA, g_h2f[prv], team, tt);   // prefetch P2's first operand
            *reinterpret_cast<float2*>(&st[eg*16      + 2*etq]) = make_float2(acc[0][0], acc[0][1]);
            *reinterpret_cast<float2*>(&st[(eg+8)*16  + 2*etq]) = make_float2(acc[0][2], acc[0][3]);
            *reinterpret_cast<float2*>(&st[eg*16 + 8  + 2*etq]) = make_float2(acc[1][0], acc[1][1]);
            *reinterpret_cast<float2*>(&st[(eg+8)*16+8+ 2*etq]) = make_float2(acc[1][2], acc[1][3]);
            __syncwarp();
            float4 gA = *reinterpret_cast<float4*>(&st[bl*16 + u0*4]);
            float4 gB = *reinterpret_cast<float4*>(&st[bl*16 + u0*4 + 4]);
            float xv  = s_xs[bglob];
            float4 bb0 = *reinterpret_cast<float4*>(&s_b1[u0*4]);
            float4 bb1 = *reinterpret_cast<float4*>(&s_b1[u0*4 + 4]);
            float4 ww0 = *reinterpret_cast<float4*>(&s_wih[u0*4]);
            float4 ww1 = *reinterpret_cast<float4*>(&s_wih[u0*4 + 4]);
            float vi = gA.x + bb0.x + xv*ww0.x;
            float vf = gA.y + bb0.y + xv*ww0.y;
            float vg = gA.z + bb0.z + xv*ww0.z;
            float vo = gA.w + bb0.w + xv*ww0.w;
            c1a = sigf(vf)*c1a + sigf(vi)*tfast(vg);
            float h0 = sigf(vo)*tfast(c1a);
            vi = gB.x + bb1.x + xv*ww1.x;
            vf = gB.y + bb1.y + xv*ww1.y;
            vg = gB.z + bb1.z + xv*ww1.z;
            vo = gB.w + bb1.w + xv*ww1.w;
            c1b = sigf(vf)*c1b + sigf(vi)*tfast(vg);
            float h1v = sigf(vo)*tfast(c1b);
            *reinterpret_cast<__half2*>(&g_h1f[cur][(size_t)bglob*HDIM + U0 + u0]) =
                __floats2half2_rn(h0, h1v);
        }
        grid_barrier(gen);

        // ---- P2: gates2 = h2_prv @ W_hh2^T  +  h1_cur @ W_ih2^T ----
        {
            float acc[2][4] = {};
            load_wait();                           // h2_prv landed (own group)
            TEAM_BAR(team);                        // teammates' groups too
            warp_gemm(acc, aBase, aswz, bB2h, bswz);
            TEAM_BAR(team);                        // A free
            load_issue(sb + SA, g_h1f[cur], team, tt);
            load_wait();
            TEAM_BAR(team);
            warp_gemm(acc, aBase, aswz, bB2i, bswz);
            // NOTE: A now holds h1_cur == next step's h1_prv (no P1 load needed)
            *reinterpret_cast<float2*>(&st[eg*16      + 2*etq]) = make_float2(acc[0][0], acc[0][1]);
            *reinterpret_cast<float2*>(&st[(eg+8)*16  + 2*etq]) = make_float2(acc[0][2], acc[0][3]);
            *reinterpret_cast<float2*>(&st[eg*16 + 8  + 2*etq]) = make_float2(acc[1][0], acc[1][1]);
            *reinterpret_cast<float2*>(&st[(eg+8)*16+8+ 2*etq]) = make_float2(acc[1][2], acc[1][3]);
            __syncwarp();
            float4 gA = *reinterpret_cast<float4*>(&st[bl*16 + u0*4]);
            float4 gB = *reinterpret_cast<float4*>(&st[bl*16 + u0*4 + 4]);
            float4 bb0 = *reinterpret_cast<float4*>(&s_b2[u0*4]);
            float4 bb1 = *reinterpret_cast<float4*>(&s_b2[u0*4 + 4]);
            float vi = gA.x + bb0.x, vf = gA.y + bb0.y;
            float vg = gA.z + bb0.z, vo = gA.w + bb0.w;
            c2a = sigf(vf)*c2a + sigf(vi)*tfast(vg);
            float h0 = sigf(vo)*tfast(c2a);
            vi = gB.x + bb1.x; vf = gB.y + bb1.y;
            vg = gB.z + bb1.z; vo = gB.w + bb1.w;
            c2b = sigf(vf)*c2b + sigf(vi)*tfast(vg);
            float h1v = sigf(vo)*tfast(c2b);
            size_t base = (size_t)bglob*HDIM + U0 + u0;
            *reinterpret_cast<__half2*>(&g_h2f[cur][base]) = __floats2half2_rn(h0, h1v);
            *reinterpret_cast<float2*>(&g_h2n[cur][base])  = make_float2(h0, h1v);
            g_h2t[cur][(size_t)(U0 + u0    )*BDIM + bglob] = h0;
            g_h2t[cur][(size_t)(U0 + u0 + 1)*BDIM + bglob] = h1v;
        }
        grid_barrier(gen);
    }

    if (tid < 32)
        out_one(g_h2n[(TOT-1)&1], Wout, s_bo[0], blk, outg + (size_t)blk*TOT + (TOT-1));
}

extern "C" void kernel_launch(void* const* d_in, const int* in_sizes, int n_in,
                              void* d_out, int out_size){
    (void)in_sizes; (void)n_in; (void)out_size;
    cudaFuncSetAttribute(lstm_persist,
                         cudaFuncAttributeMaxDynamicSharedMemorySize, SMEM_BYTES);
    const float* x    = (const float*)d_in[0];
    const float* Wih1 = (const float*)d_in[1];
    const float* Whh1 = (const float*)d_in[2];
    const float* bih1 = (const float*)d_in[3];
    const float* bhh1 = (const float*)d_in[4];
    const float* Wih2 = (const float*)d_in[5];
    const float* Whh2 = (const float*)d_in[6];
    const float* bih2 = (const float*)d_in[7];
    const float* bhh2 = (const float*)d_in[8];
    const float* Wout = (const float*)d_in[9];
    const float* bout = (const float*)d_in[10];
    float* out = (float*)d_out;

    lstm_reset<<<1, NBLK>>>();
    lstm_persist<<<NBLK, NTHR, SMEM_BYTES>>>(
        x, Wih1, Whh1, bih1, bhh1, Wih2, Whh2, bih2, bhh2, Wout, bout, out);
}

// round 17
// speedup vs baseline: 1.9535x; 1.8258x over previous
#include <cuda_runtime.h>
#include <cuda_fp16.h>
#include <cstdint>

#define NBLK 128
#define NTHR 256
#define HDIM 512
#define BDIM 128
#define TIN  512
#define TOT  544
#define BH   (BDIM*HDIM)

// SMEM byte offsets (all 1KB-aligned)
#define SA    0           // A tile: 128 rows x 1024B fp16, swizzled
#define SW1   131072      // 3 weight tiles: 16 rows x 1024B fp16 each
#define SW2I  147456
#define SW2H  163840
#define SGATE 180224      // 8 warps x 16x16 f32 = 8192
#define SMISC 188416
#define SXS   (SMISC)         // 128 f32
#define SRED  (SMISC+512)     // 256 f32
#define SB1   (SMISC+1536)    // 16 f32
#define SWIH  (SMISC+1600)    // 16 f32
#define SB2   (SMISC+1664)    // 16 f32
#define SBOUT (SMISC+1728)    // 1 f32
#define SMEM_BYTES (SMISC+2048)

__device__ __half  g_h1f[2][BH];   // [buf][b][k] fp16
__device__ __half  g_h2f[2][BH];
__device__ float   g_h2n[2][BH];   // [buf][b][k] fp32 (output dots)
__device__ float   g_h2t[2][BH];   // [buf][k][b] fp32 (future-phase dot)
__device__ float   g_xt[TIN*BDIM]; // x transposed [t][b] (coalesced phase-X)
__device__ unsigned g_bar;

static __device__ __forceinline__ uint32_t smem_u32(const void* p){
    uint32_t a;
    asm("{ .reg .u64 t; cvta.to.shared.u64 t, %1; cvt.u32.u64 %0, t; }" : "=r"(a) : "l"(p));
    return a;
}
static __device__ __forceinline__ float sigf(float x){ return 1.0f/(1.0f+__expf(-x)); }
static __device__ __forceinline__ float tfast(float x){ return 2.0f*sigf(2.0f*x) - 1.0f; }

// R13's contended-atomic grid barrier (empirically faster than flag array)
static __device__ __forceinline__ void grid_barrier(unsigned& gen){
    __threadfence();
    __syncthreads();
    if (threadIdx.x == 0){
        unsigned target = gen + NBLK;
        atomicAdd(&g_bar, 1u);
        unsigned v;
        do { asm volatile("ld.acquire.gpu.u32 %0, [%1];" : "=r"(v) : "l"(&g_bar)); }
        while (v < target);
    }
    gen += NBLK;
    __syncthreads();
}

#define TEAM_BAR(team) asm volatile("bar.sync %0, 128;" :: "r"(1+(team)) : "memory")

// issue cp.async for 64 batch rows (team half) of h [.][512] fp16 -> SMEM A, L2-only.
static __device__ __forceinline__ void load_issue(uint32_t saAddr,
                                                  const __half* __restrict__ src,
                                                  int team, int tt){
    #pragma unroll
    for (int j = 0; j < 32; ++j){
        int i  = tt + j*128;
        int m  = team*64 + (i >> 6);
        int u8 = i & 63;
        uint32_t dst = (saAddr + (uint32_t)(m*1024 + u8*16)) ^ (uint32_t)((m & 7) << 4);
        const __half* s = src + (size_t)m*HDIM + u8*8;
        asm volatile("cp.async.cg.shared.global [%0], [%1], 16;"
                     :: "r"(dst), "l"(s) : "memory");
    }
    asm volatile("cp.async.commit_group;" ::: "memory");
}
static __device__ __forceinline__ void load_wait(){
    asm volatile("cp.async.wait_group 0;" ::: "memory");
}

// warp GEMM: acc[2][4] += A(16 rows x 512) * B(16 x 512)^T, k-tiles of 16
static __device__ __forceinline__ void warp_gemm(float (&acc)[2][4],
                                                 uint32_t aBase, uint32_t aswz,
                                                 uint32_t bBase, uint32_t bswz){
    #pragma unroll 8
    for (int kt = 0; kt < 32; ++kt){
        uint32_t aa = (aBase + (uint32_t)(kt*32)) ^ aswz;
        uint32_t ba = (bBase + (uint32_t)(kt*32)) ^ bswz;
        uint32_t a0,a1,a2,a3, b0,b1,b2,b3;
        asm volatile("ldmatrix.sync.aligned.m8n8.x4.shared.b16 {%0,%1,%2,%3}, [%4];"
            : "=r"(a0),"=r"(a1),"=r"(a2),"=r"(a3) : "r"(aa));
        asm volatile("ldmatrix.sync.aligned.m8n8.x4.shared.b16 {%0,%1,%2,%3}, [%4];"
            : "=r"(b0),"=r"(b1),"=r"(b2),"=r"(b3) : "r"(ba));
        asm volatile("mma.sync.aligned.m16n8k16.row.col.f32.f16.f16.f32 "
            "{%0,%1,%2,%3}, {%4,%5,%6,%7}, {%8,%9}, {%0,%1,%2,%3};"
            : "+f"(acc[0][0]),"+f"(acc[0][1]),"+f"(acc[0][2]),"+f"(acc[0][3])
            : "r"(a0),"r"(a1),"r"(a2),"r"(a3), "r"(b0),"r"(b1));
        asm volatile("mma.sync.aligned.m16n8k16.row.col.f32.f16.f16.f32 "
            "{%0,%1,%2,%3}, {%4,%5,%6,%7}, {%8,%9}, {%0,%1,%2,%3};"
            : "+f"(acc[1][0]),"+f"(acc[1][1]),"+f"(acc[1][2]),"+f"(acc[1][3])
            : "r"(a0),"r"(a1),"r"(a2),"r"(a3), "r"(b2),"r"(b3));
    }
}

// out[b] = dot(h2n[b,:], Wout) + bias; warp 0 (tid<32)
static __device__ __forceinline__ void out_one(
    const float* __restrict__ h2n, const float* __restrict__ Wout,
    float bout, int b, float* dst)
{
    const int lane = threadIdx.x;
    const float4* hp = reinterpret_cast<const float4*>(h2n) + (size_t)b*(HDIM/4);
    const float4* wp = reinterpret_cast<const float4*>(Wout);
    float s = 0.f;
    #pragma unroll
    for (int q = lane; q < HDIM/4; q += 32){
        float4 hv = __ldcg(hp + q); float4 w = __ldg(wp + q);
        s += hv.x*w.x + hv.y*w.y + hv.z*w.z + hv.w*w.w;
    }
    #pragma unroll
    for (int o = 16; o; o >>= 1) s += __shfl_xor_sync(0xffffffffu, s, o);
    if (lane == 0) *dst = s + bout;
}

__global__ void lstm_reset(){ g_bar = 0u; }

__global__ void __launch_bounds__(NTHR, 1) lstm_persist(
    const float* __restrict__ xg,
    const float* __restrict__ Wih1, const float* __restrict__ Whh1,
    const float* __restrict__ bih1, const float* __restrict__ bhh1,
    const float* __restrict__ Wih2, const float* __restrict__ Whh2,
    const float* __restrict__ bih2, const float* __restrict__ bhh2,
    const float* __restrict__ Wout, const float* __restrict__ boutp,
    float* __restrict__ outg)
{
    extern __shared__ __align__(128) char sm[];
    const uint32_t sb = smem_u32(sm);
    float* s_gate = reinterpret_cast<float*>(sm + SGATE);
    float* s_xs   = reinterpret_cast<float*>(sm + SXS);
    float* s_red  = reinterpret_cast<float*>(sm + SRED);
    float* s_b1   = reinterpret_cast<float*>(sm + SB1);
    float* s_wih  = reinterpret_cast<float*>(sm + SWIH);
    float* s_b2   = reinterpret_cast<float*>(sm + SB2);
    float* s_bo   = reinterpret_cast<float*>(sm + SBOUT);

    const int tid  = threadIdx.x;
    const int blk  = blockIdx.x;
    const int U0   = blk * 4;
    const int wid  = tid >> 5;
    const int lane = tid & 31;
    const int team = tid >> 7;
    const int tt   = tid & 127;

    // ldmatrix lane addressing
    const int grp = lane >> 3, l7 = lane & 7;
    const int am  = (wid << 4) + l7 + ((grp & 1) << 3);
    const uint32_t aBase = sb + SA + (uint32_t)(am*1024 + ((grp >> 1) << 4));
    const uint32_t aswz  = (uint32_t)((am & 7) << 4);
    const int bn  = l7 + ((grp >> 1) << 3);
    const uint32_t bOff  = (uint32_t)(bn*1024 + ((grp & 1) << 4));
    const uint32_t bswz  = (uint32_t)((bn & 7) << 4);
    const uint32_t bB1   = sb + SW1  + bOff;
    const uint32_t bB2i  = sb + SW2I + bOff;
    const uint32_t bB2h  = sb + SW2H + bOff;

    // ---- one-time staging ----
    for (int idx = tid; idx < 16*HDIM; idx += NTHR){
        int n = idx >> 9, k = idx & 511;
        int uu = n >> 2, gg = n & 3;
        size_t j = (size_t)(gg*HDIM + U0 + uu) * HDIM + k;
        uint32_t rel = (uint32_t)(n*1024 + 2*k);
        uint32_t sw  = (uint32_t)((n & 7) << 4);
        unsigned short v1 = __half_as_ushort(__float2half(Whh1[j]));
        unsigned short v2 = __half_as_ushort(__float2half(Wih2[j]));
        unsigned short v3 = __half_as_ushort(__float2half(Whh2[j]));
        asm volatile("st.shared.u16 [%0], %1;" :: "r"((sb + SW1  + rel) ^ sw), "h"(v1));
        asm volatile("st.shared.u16 [%0], %1;" :: "r"((sb + SW2I + rel) ^ sw), "h"(v2));
        asm volatile("st.shared.u16 [%0], %1;" :: "r"((sb + SW2H + rel) ^ sw), "h"(v3));
    }
    if (tid < 16){
        int uu = tid >> 2, gg = tid & 3;
        int j = gg*HDIM + U0 + uu;
        s_b1[tid]  = bih1[j] + bhh1[j];
        s_b2[tid]  = bih2[j] + bhh2[j];
        s_wih[tid] = Wih1[j];
    }
    if (tid == 0) s_bo[0] = boutp[0];
    // x transpose: CTA blk owns batch row blk (coalesced read, one-time strided write)
    for (int tq = tid; tq < TIN; tq += NTHR)
        g_xt[(size_t)tq*BDIM + blk] = xg[(size_t)blk*TIN + tq];
    for (int i = tid; i < 4*BDIM; i += NTHR){
        int kk = U0 + (i >> 7), bb = i & 127;
        size_t on = (size_t)bb*HDIM + kk;
        size_t ot = (size_t)kk*BDIM + bb;
        g_h1f[0][on] = __float2half(0.f); g_h1f[1][on] = __float2half(0.f);
        g_h2f[0][on] = __float2half(0.f); g_h2f[1][on] = __float2half(0.f);
        g_h2n[0][on] = 0.f; g_h2n[1][on] = 0.f;
        g_h2t[0][ot] = 0.f; g_h2t[1][ot] = 0.f;
    }
    unsigned gen = 0;
    grid_barrier(gen);               // zeros + x-transpose visible chip-wide

    // preload A with h1f[1] (= prv for t=0)
    load_issue(sb + SA, g_h1f[1], team, tt);
    load_wait();
    __syncthreads();

    // epilogue indices
    const int eg = lane >> 2, etq = lane & 3;
    const int bl = lane >> 1, u0 = (lane & 1) * 2;
    const int bglob = (wid << 4) + bl;
    float* st = s_gate + wid*256;
    float c1a = 0.f, c1b = 0.f, c2a = 0.f, c2b = 0.f;

    for (int t = 0; t < TOT; ++t){
        const int cur = t & 1, prv = cur ^ 1;

        // ---- Phase X (coalesced x fetch) ----
        if (t < TIN){
            if (tid < BDIM) s_xs[tid] = __ldcg(&g_xt[(size_t)t*BDIM + tid]);
            if (t > 0 && tid < 32)
                out_one(g_h2n[prv], Wout, s_bo[0], blk, outg + (size_t)blk*TOT + (t-1));
        } else {
            int b = tid & 127, half = tid >> 7;
            const float* hp = g_h2t[prv] + (size_t)half*(HDIM/2)*BDIM + b;
            const float* wp = Wout + half*(HDIM/2);
            float s = 0.f;
            #pragma unroll 8
            for (int q = 0; q < HDIM/2; ++q)
                s += __ldcg(hp + (size_t)q*BDIM) * __ldg(wp + q);
            s_red[tid] = s;
            __syncthreads();
            if (tid < BDIM) s_xs[tid] = s_red[tid] + s_red[tid+128] + s_bo[0];
        }
        __syncthreads();
        if (t >= TIN && tid == 0) outg[(size_t)blk*TOT + (t-1)] = s_xs[blk];

        // ---- P1: gates1 = h1_prv @ W_hh1^T   (A already holds h1_prv) ----
        {
            float acc[2][4] = {};
            warp_gemm(acc, aBase, aswz, bB1, bswz);
            TEAM_BAR(team);                            // team A-reads done
            load_issue(sb + SA, g_h2f[prv], team, tt); // prefetch P2's first operand
            *reinterpret_cast<float2*>(&st[eg*16      + 2*etq]) = make_float2(acc[0][0], acc[0][1]);
            *reinterpret_cast<float2*>(&st[(eg+8)*16  + 2*etq]) = make_float2(acc[0][2], acc[0][3]);
            *reinterpret_cast<float2*>(&st[eg*16 + 8  + 2*etq]) = make_float2(acc[1][0], acc[1][1]);
            *reinterpret_cast<float2*>(&st[(eg+8)*16+8+ 2*etq]) = make_float2(acc[1][2], acc[1][3]);
            __syncwarp();
            float4 gA = *reinterpret_cast<float4*>(&st[bl*16 + u0*4]);
            float4 gB = *reinterpret_cast<float4*>(&st[bl*16 + u0*4 + 4]);
            float xv  = s_xs[bglob];
            float4 bb0 = *reinterpret_cast<float4*>(&s_b1[u0*4]);
            float4 bb1 = *reinterpret_cast<float4*>(&s_b1[u0*4 + 4]);
            float4 ww0 = *reinterpret_cast<float4*>(&s_wih[u0*4]);
            float4 ww1 = *reinterpret_cast<float4*>(&s_wih[u0*4 + 4]);
            float vi = gA.x + bb0.x + xv*ww0.x;
            float vf = gA.y + bb0.y + xv*ww0.y;
            float vg = gA.z + bb0.z + xv*ww0.z;
            float vo = gA.w + bb0.w + xv*ww0.w;
            c1a = sigf(vf)*c1a + sigf(vi)*tfast(vg);
            float h0 = sigf(vo)*tfast(c1a);
            vi = gB.x + bb1.x + xv*ww1.x;
            vf = gB.y + bb1.y + xv*ww1.y;
            vg = gB.z + bb1.z + xv*ww1.z;
            vo = gB.w + bb1.w + xv*ww1.w;
            c1b = sigf(vf)*c1b + sigf(vi)*tfast(vg);
            float h1v = sigf(vo)*tfast(c1b);
            *reinterpret_cast<__half2*>(&g_h1f[cur][(size_t)bglob*HDIM + U0 + u0]) =
                __floats2half2_rn(h0, h1v);
        }
        grid_barrier(gen);

        // ---- P2: gates2 = h2_prv @ W_hh2^T  +  h1_cur @ W_ih2^T ----
        {
            float acc[2][4] = {};
            load_wait();                           // h2_prv landed (own thread's group)
            TEAM_BAR(team);                        // teammates' groups visible too
            warp_gemm(acc, aBase, aswz, bB2h, bswz);
            TEAM_BAR(team);                        // A free
            load_issue(sb + SA, g_h1f[cur], team, tt);
            load_wait();
            TEAM_BAR(team);
            warp_gemm(acc, aBase, aswz, bB2i, bswz);
            // A now holds h1_cur == next step's h1_prv (P1 load elided)
            *reinterpret_cast<float2*>(&st[eg*16      + 2*etq]) = make_float2(acc[0][0], acc[0][1]);
            *reinterpret_cast<float2*>(&st[(eg+8)*16  + 2*etq]) = make_float2(acc[0][2], acc[0][3]);
            *reinterpret_cast<float2*>(&st[eg*16 + 8  + 2*etq]) = make_float2(acc[1][0], acc[1][1]);
            *reinterpret_cast<float2*>(&st[(eg+8)*16+8+ 2*etq]) = make_float2(acc[1][2], acc[1][3]);
            __syncwarp();
            float4 gA = *reinterpret_cast<float4*>(&st[bl*16 + u0*4]);
            float4 gB = *reinterpret_cast<float4*>(&st[bl*16 + u0*4 + 4]);
            float4 bb0 = *reinterpret_cast<float4*>(&s_b2[u0*4]);
            float4 bb1 = *reinterpret_cast<float4*>(&s_b2[u0*4 + 4]);
            float vi = gA.x + bb0.x, vf = gA.y + bb0.y;
            float vg = gA.z + bb0.z, vo = gA.w + bb0.w;
            c2a = sigf(vf)*c2a + sigf(vi)*tfast(vg);
            float h0 = sigf(vo)*tfast(c2a);
            vi = gB.x + bb1.x; vf = gB.y + bb1.y;
            vg = gB.z + bb1.z; vo = gB.w + bb1.w;
            c2b = sigf(vf)*c2b + sigf(vi)*tfast(vg);
            float h1v = sigf(vo)*tfast(c2b);
            size_t base = (size_t)bglob*HDIM + U0 + u0;
            *reinterpret_cast<__half2*>(&g_h2f[cur][base]) = __floats2half2_rn(h0, h1v);
            *reinterpret_cast<float2*>(&g_h2n[cur][base])  = make_float2(h0, h1v);
            g_h2t[cur][(size_t)(U0 + u0    )*BDIM + bglob] = h0;
            g_h2t[cur][(size_t)(U0 + u0 + 1)*BDIM + bglob] = h1v;
        }
        grid_barrier(gen);
    }

    if (tid < 32)
        out_one(g_h2n[(TOT-1)&1], Wout, s_bo[0], blk, outg + (size_t)blk*TOT + (TOT-1));
}

extern "C" void kernel_launch(void* const* d_in, const int* in_sizes, int n_in,
                              void* d_out, int out_size){
    (void)in_sizes; (void)n_in; (void)out_size;
    cudaFuncSetAttribute(lstm_persist,
                         cudaFuncAttributeMaxDynamicSharedMemorySize, SMEM_BYTES);
    const float* x    = (const float*)d_in[0];
    const float* Wih1 = (const float*)d_in[1];
    const float* Whh1 = (const float*)d_in[2];
    const float* bih1 = (const float*)d_in[3];
    const float* bhh1 = (const float*)d_in[4];
    const float* Wih2 = (const float*)d_in[5];
    const float* Whh2 = (const float*)d_in[6];
    const float* bih2 = (const float*)d_in[7];
    const float* bhh2 = (const float*)d_in[8];
    const float* Wout = (const float*)d_in[9];
    const float* bout = (const float*)d_in[10];
    float* out = (float*)d_out;

    lstm_reset<<<1, 1>>>();
    lstm_persist<<<NBLK, NTHR, SMEM_BYTES>>>(
        x, Wih1, Whh1, bih1, bhh1, Wih2, Whh2, bih2, bhh2, Wout, bout, out);
}